// round 3
// baseline (speedup 1.0000x reference)
#include <cuda_runtime.h>
#include <math.h>

#define BB 32
#define NN 1000
#define BN (BB*NN)
#define DD 64
#define HID 256
#define OBS 147
#define KSEL 500
#define NEGV (-1e8f)

// ---------------- scratch (device globals; no allocation) ----------------
__device__ float g_distT[(size_t)NN*NN];          // dist[j,i] -> distT[i,j]
__device__ float g_x[(size_t)BN*15];
__device__ float g_h[(size_t)BN*DD];
__device__ float g_hs[BN];
__device__ float g_hd[BN];
__device__ float g_comp[(size_t)BN*DD];
__device__ float g_coop[(size_t)BN*DD];
__device__ unsigned char g_adjT[(size_t)BN*NN];   // adj[b,j,i] -> adjT[b,i,j]
__device__ float g_xp[(size_t)BN*HID];
__device__ float g_scores[2*BN];                  // [0..BN)=f, [BN..2BN)=d
__device__ int   g_flag4;                         // 1 if bool inputs are int32, 0 if 1-byte

// ---------------- bool-width detection ----------------
// If bools are int32 (little-endian 0/1), every non-word-aligned byte is 0.
// If bools are 1-byte with ~50% density, non-aligned nonzero bytes appear
// within the first few dozen bytes with overwhelming probability.
__global__ void detect_kernel(const unsigned char* p, int nbytes) {
    __shared__ int any;
    if (threadIdx.x == 0) any = 0;
    __syncthreads();
    int loc = 0;
    for (int i = threadIdx.x; i < nbytes; i += blockDim.x)
        if ((i & 3) && p[i]) loc = 1;
    if (loc) any = 1;
    __syncthreads();
    if (threadIdx.x == 0) g_flag4 = any ? 0 : 1;
}

__device__ __forceinline__ bool bget(const void* p, size_t idx, int f4) {
    return f4 ? (((const int*)p)[idx] != 0) : (((const unsigned char*)p)[idx] != 0);
}

// ---------------- transposes ----------------
__global__ void distT_kernel(const float* __restrict__ dist) {
    __shared__ float t[32][33];
    int i0 = blockIdx.x * 32, j0 = blockIdx.y * 32;
    for (int r = 0; r < 4; r++) {
        int j = j0 + threadIdx.y + r * 8, i = i0 + threadIdx.x;
        t[threadIdx.y + r * 8][threadIdx.x] = (j < NN && i < NN) ? dist[(size_t)j * NN + i] : 0.f;
    }
    __syncthreads();
    for (int r = 0; r < 4; r++) {
        int i = i0 + threadIdx.y + r * 8, j = j0 + threadIdx.x;
        if (i < NN && j < NN) g_distT[(size_t)i * NN + j] = t[threadIdx.x][threadIdx.y + r * 8];
    }
}

__global__ void adjT_kernel(const void* __restrict__ adj) {
    __shared__ unsigned char t[32][33];
    int b = blockIdx.z;
    int i0 = blockIdx.x * 32, j0 = blockIdx.y * 32;
    int f4 = g_flag4;
    size_t base = (size_t)b * NN * NN;
    for (int r = 0; r < 4; r++) {
        int j = j0 + threadIdx.y + r * 8, i = i0 + threadIdx.x;
        unsigned char v = 0;
        if (j < NN && i < NN) v = bget(adj, base + (size_t)j * NN + i, f4) ? 1 : 0;
        t[threadIdx.y + r * 8][threadIdx.x] = v;
    }
    __syncthreads();
    for (int r = 0; r < 4; r++) {
        int i = i0 + threadIdx.y + r * 8, j = j0 + threadIdx.x;
        if (i < NN && j < NN) g_adjT[base + (size_t)i * NN + j] = t[threadIdx.x][threadIdx.y + r * 8];
    }
}

// ---------------- x = [cs(4), tp(2), vf(9)] ----------------
__global__ void buildx_kernel(const int* __restrict__ op_idx, const float* __restrict__ vf,
                              const float* __restrict__ cs_tab, const float* __restrict__ tp_tab) {
    int idx = blockIdx.x * blockDim.x + threadIdx.x;
    if (idx >= BN) return;
    int n = idx % NN;
    float* xr = g_x + (size_t)idx * 15;
    int op = op_idx[idx];
#pragma unroll
    for (int c = 0; c < 4; c++) xr[c] = cs_tab[n * 4 + c];
    xr[4] = tp_tab[op * 2 + 0];
    xr[5] = tp_tab[op * 2 + 1];
#pragma unroll
    for (int c = 0; c < 9; c++) xr[6 + c] = vf[(size_t)idx * 9 + c];
}

// ---------------- h = x @ W, hd = h.adst, hs = h.asrc ----------------
__global__ __launch_bounds__(256) void h_kernel(const float* __restrict__ xa, int Fa,
                                                const float* __restrict__ xb, int Fb,
                                                const float* __restrict__ W,
                                                const float* __restrict__ asrc,
                                                const float* __restrict__ adst) {
    __shared__ float xs[4][80];
    __shared__ float red[4][2][2];
    int nl = threadIdx.x >> 6, d = threadIdx.x & 63;
    size_t gn = (size_t)blockIdx.x * 4 + nl;
    for (int f = d; f < Fa; f += 64) xs[nl][f] = xa[gn * Fa + f];
    for (int f = d; f < Fb; f += 64) xs[nl][Fa + f] = xb[gn * Fb + f];
    __syncthreads();
    int F = Fa + Fb;
    float acc = 0.f;
    for (int f = 0; f < F; f++) acc = fmaf(xs[nl][f], W[f * DD + d], acc);
    g_h[gn * DD + d] = acc;
    float p1 = acc * adst[d], p2 = acc * asrc[d];
    for (int o = 16; o; o >>= 1) {
        p1 += __shfl_xor_sync(0xffffffffu, p1, o);
        p2 += __shfl_xor_sync(0xffffffffu, p2, o);
    }
    if ((d & 31) == 0) { red[nl][d >> 5][0] = p1; red[nl][d >> 5][1] = p2; }
    __syncthreads();
    if (threadIdx.x < 4) {
        size_t g2 = (size_t)blockIdx.x * 4 + threadIdx.x;
        g_hd[g2] = red[threadIdx.x][0][0] + red[threadIdx.x][1][0];
        g_hs[g2] = red[threadIdx.x][0][1] + red[threadIdx.x][1][1];
    }
}

// ---------------- fused GAT: e -> online softmax -> alpha @ h -> elu ----------------
// 256 thr = 8 warps; each warp: 4 dst nodes, each lane: 2 feature dims.
__global__ __launch_bounds__(256) void gat_kernel(const float* __restrict__ wdp,
                                                  float* __restrict__ outrep) {
    const float wd = *wdp;
    int b = blockIdx.y;
    int w = threadIdx.x >> 5, lane = threadIdx.x & 31;
    __shared__ float h_sm[64][64];
    __shared__ float hs_sm[64];
    __shared__ float p_sm[8][64][4];
    int ibase = blockIdx.x * 32 + w * 4;
    float hdv[4], m[4], s[4];
    float2 acc[4];
    const unsigned char* arow[4];
    const float* drow[4];
    bool val[4];
#pragma unroll
    for (int g = 0; g < 4; g++) {
        int ig = ibase + g;
        val[g] = (ig < NN);
        int igc = val[g] ? ig : 0;
        hdv[g] = g_hd[b * NN + igc];
        arow[g] = g_adjT + ((size_t)b * NN + igc) * NN;
        drow[g] = g_distT + (size_t)igc * NN;
        m[g] = -INFINITY; s[g] = 0.f; acc[g] = make_float2(0.f, 0.f);
    }
    const float* hb = g_h + (size_t)b * NN * DD;
    const float* hsb = g_hs + b * NN;

    for (int j0 = 0; j0 < NN; j0 += 64) {
        __syncthreads();
        for (int t = threadIdx.x; t < 64 * 64 / 4; t += 256) {
            int j = t >> 4, d4 = (t & 15) << 2;
            int jj = j0 + j;
            float4 v = make_float4(0.f, 0.f, 0.f, 0.f);
            if (jj < NN) v = *(const float4*)(hb + (size_t)jj * DD + d4);
            *(float4*)&h_sm[j][d4] = v;
        }
        if (threadIdx.x < 64) {
            int jj = j0 + threadIdx.x;
            hs_sm[threadIdx.x] = (jj < NN) ? hsb[jj] : 0.f;
        }
        __syncthreads();

        int jj0 = j0 + lane, jj1 = j0 + lane + 32;
        bool in0 = jj0 < NN, in1 = jj1 < NN;
        float hsv0 = hs_sm[lane], hsv1 = hs_sm[lane + 32];
        float e0[4], e1[4], p0[4], p1[4];
#pragma unroll
        for (int g = 0; g < 4; g++) {
            e0[g] = -INFINITY; e1[g] = -INFINITY;
            if (val[g]) {
                if (in0 && arow[g][jj0]) {
                    float ev = hdv[g] + hsv0 + wd * __ldg(&drow[g][jj0]);
                    e0[g] = (ev >= 0.f) ? ev : 0.2f * ev;
                }
                if (in1 && arow[g][jj1]) {
                    float ev = hdv[g] + hsv1 + wd * __ldg(&drow[g][jj1]);
                    e1[g] = (ev >= 0.f) ? ev : 0.2f * ev;
                }
            }
        }
#pragma unroll
        for (int g = 0; g < 4; g++) {
            float cm = fmaxf(e0[g], e1[g]);
            for (int o = 16; o; o >>= 1) cm = fmaxf(cm, __shfl_xor_sync(0xffffffffu, cm, o));
            float mn = fmaxf(m[g], cm);
            float r = (mn == -INFINITY) ? 1.f : __expf(m[g] - mn);
            p0[g] = (e0[g] == -INFINITY) ? 0.f : __expf(e0[g] - mn);
            p1[g] = (e1[g] == -INFINITY) ? 0.f : __expf(e1[g] - mn);
            float cs = p0[g] + p1[g];
            for (int o = 16; o; o >>= 1) cs += __shfl_xor_sync(0xffffffffu, cs, o);
            s[g] = s[g] * r + cs;
            acc[g].x *= r; acc[g].y *= r;
            m[g] = mn;
        }
        *(float4*)&p_sm[w][lane][0]      = make_float4(p0[0], p0[1], p0[2], p0[3]);
        *(float4*)&p_sm[w][lane + 32][0] = make_float4(p1[0], p1[1], p1[2], p1[3]);
        __syncwarp();
#pragma unroll 8
        for (int j = 0; j < 64; j++) {
            float4 p4 = *(const float4*)&p_sm[w][j][0];
            float2 hv = *(const float2*)&h_sm[j][lane * 2];
            acc[0].x = fmaf(p4.x, hv.x, acc[0].x); acc[0].y = fmaf(p4.x, hv.y, acc[0].y);
            acc[1].x = fmaf(p4.y, hv.x, acc[1].x); acc[1].y = fmaf(p4.y, hv.y, acc[1].y);
            acc[2].x = fmaf(p4.z, hv.x, acc[2].x); acc[2].y = fmaf(p4.z, hv.y, acc[2].y);
            acc[3].x = fmaf(p4.w, hv.x, acc[3].x); acc[3].y = fmaf(p4.w, hv.y, acc[3].y);
        }
    }
#pragma unroll
    for (int g = 0; g < 4; g++) {
        if (!val[g]) continue;
        float inv = (s[g] > 0.f) ? 1.f / s[g] : 0.f;
        float vx = acc[g].x * inv, vy = acc[g].y * inv;
        vx = (vx > 0.f) ? vx : expm1f(vx);
        vy = (vy > 0.f) ? vy : expm1f(vy);
        int ig = ibase + g;
        *(float2*)&outrep[((size_t)b * NN + ig) * DD + lane * 2] = make_float2(vx, vy);
    }
}

// ---------------- x_p = sag @ Wp + bp ----------------
__global__ __launch_bounds__(256) void xp_kernel(const int* __restrict__ time_idx,
                                                 const int* __restrict__ op_idx,
                                                 const float* __restrict__ vf,
                                                 const float* __restrict__ time_tab,
                                                 const float* __restrict__ cs_tab,
                                                 const float* __restrict__ tp_tab,
                                                 const float* __restrict__ Wp,
                                                 const float* __restrict__ bp,
                                                 float* __restrict__ xp) {
    __shared__ float sag[OBS][8];
    int w = threadIdx.x >> 5, lane = threadIdx.x & 31;
    size_t gn0 = (size_t)blockIdx.x * 8;
    {
        size_t gn = gn0 + w;
        int n = (int)(gn % NN);
        int ti = time_idx[gn], op = op_idx[gn];
        for (int f = lane; f < OBS; f += 32) {
            float v;
            if (f < 4)       v = time_tab[ti * 4 + f];
            else if (f < 8)  v = cs_tab[n * 4 + (f - 4)];
            else if (f < 10) v = tp_tab[op * 2 + (f - 8)];
            else if (f < 19) v = vf[gn * 9 + (f - 10)];
            else if (f < 83) v = g_comp[gn * 64 + (f - 19)];
            else             v = g_coop[gn * 64 + (f - 83)];
            sag[f][w] = v;
        }
    }
    __syncthreads();
    int h = threadIdx.x;
    float bv = bp[h];
    float acc[8];
#pragma unroll
    for (int nl = 0; nl < 8; nl++) acc[nl] = bv;
#pragma unroll 4
    for (int f = 0; f < OBS; f++) {
        float wv = Wp[f * HID + h];
        float4 s0 = *(const float4*)&sag[f][0];
        float4 s1 = *(const float4*)&sag[f][4];
        acc[0] = fmaf(s0.x, wv, acc[0]); acc[1] = fmaf(s0.y, wv, acc[1]);
        acc[2] = fmaf(s0.z, wv, acc[2]); acc[3] = fmaf(s0.w, wv, acc[3]);
        acc[4] = fmaf(s1.x, wv, acc[4]); acc[5] = fmaf(s1.y, wv, acc[5]);
        acc[6] = fmaf(s1.z, wv, acc[6]); acc[7] = fmaf(s1.w, wv, acc[7]);
    }
#pragma unroll
    for (int nl = 0; nl < 8; nl++) xp[(gn0 + nl) * HID + h] = acc[nl];
}

// ---------------- scores = xp . vpd / vpf ----------------
__global__ void scores_kernel(const float* __restrict__ xp, const float* __restrict__ vpd,
                              const float* __restrict__ vpf) {
    int w = threadIdx.x >> 5, lane = threadIdx.x & 31;
    size_t gn = (size_t)blockIdx.x * 8 + w;
    const float* r = xp + gn * HID;
    float sd = 0.f, sf = 0.f;
#pragma unroll
    for (int k = 0; k < 8; k++) {
        int hh = lane + 32 * k;
        float v = r[hh];
        sd = fmaf(v, vpd[hh], sd);
        sf = fmaf(v, vpf[hh], sf);
    }
    for (int o = 16; o; o >>= 1) {
        sd += __shfl_xor_sync(0xffffffffu, sd, o);
        sf += __shfl_xor_sync(0xffffffffu, sf, o);
    }
    if (lane == 0) { g_scores[gn] = sf; g_scores[BN + gn] = sd; }
}

// ---------------- gated top-k pooling ----------------
__global__ __launch_bounds__(256) void pool_kernel(const float* __restrict__ xp,
                                                   const void* __restrict__ dpcs,
                                                   float* __restrict__ out) {
    int b = blockIdx.x, type = blockIdx.y;  // 0 = f (~mark), 1 = d (mark)
    __shared__ float sc[1024];
    __shared__ float sraw[NN];
    __shared__ float red[256];
    int f4 = g_flag4;
    const float* srow = g_scores + (size_t)type * BN + (size_t)b * NN;

    // global max over raw scores (reference shifts BEFORE masking)
    float lm = -INFINITY;
    for (int n = threadIdx.x; n < NN; n += 256) lm = fmaxf(lm, srow[n]);
    red[threadIdx.x] = lm;
    __syncthreads();
    for (int o = 128; o; o >>= 1) {
        if (threadIdx.x < o) red[threadIdx.x] = fmaxf(red[threadIdx.x], red[threadIdx.x + o]);
        __syncthreads();
    }
    float gm = red[0];
    __syncthreads();

    for (int n = threadIdx.x; n < 1024; n += 256) {
        float v = -INFINITY;
        if (n < NN) {
            bool mk = bget(dpcs, (size_t)b * NN + n, f4);
            bool valid = type ? mk : !mk;
            float sv = valid ? (srow[n] - gm) : NEGV;
            sraw[n] = sv;
            v = sv;
        }
        sc[n] = v;
    }
    __syncthreads();

    // bitonic sort, descending
    for (int k = 2; k <= 1024; k <<= 1)
        for (int j = k >> 1; j > 0; j >>= 1) {
            for (int i = threadIdx.x; i < 1024; i += 256) {
                int ixj = i ^ j;
                if (ixj > i) {
                    float a = sc[i], c = sc[ixj];
                    bool dirAsc = (i & k) == 0;
                    bool sw = dirAsc ? (a < c) : (a > c);
                    if (sw) { sc[i] = c; sc[ixj] = a; }
                }
            }
            __syncthreads();
        }
    float th = sc[KSEL - 1];
    float mx = sc[0];

    float part = 0.f;
    for (int n = threadIdx.x; n < NN; n += 256) {
        float sv = sraw[n];
        float p = (sv >= th) ? __expf(sv - mx) : 0.f;
        sraw[n] = p;
        part += p;
    }
    __syncthreads();
    red[threadIdx.x] = part;
    __syncthreads();
    for (int o = 128; o; o >>= 1) {
        if (threadIdx.x < o) red[threadIdx.x] += red[threadIdx.x + o];
        __syncthreads();
    }
    float invS = 1.f / red[0];

    int h = threadIdx.x;
    const float* xpb = xp + (size_t)b * NN * HID + h;
    float sum = 0.f, mxv = -INFINITY;
    for (int n = 0; n < NN; n++) {
        float wgt = sraw[n] * invS;
        float v = xpb[(size_t)n * HID];
        float xv = wgt * v;
        sum += xv;
        mxv = fmaxf(mxv, xv);
    }
    float* ob = out + (size_t)b * 1024 + type * 512;
    ob[h] = sum;
    ob[256 + h] = mxv;
}

// ---------------- launch ----------------
extern "C" void kernel_launch(void* const* d_in, const int* in_sizes, int n_in,
                              void* d_out, int out_size) {
    const int*   time_idx = (const int*)d_in[0];
    const int*   op_idx   = (const int*)d_in[1];
    const float* vf       = (const float*)d_in[2];
    const void*  dpcs     = d_in[3];
    const void*  adjc     = d_in[4];
    const void*  adjo     = d_in[5];
    const float* dist     = (const float*)d_in[6];
    const float* time_tab = (const float*)d_in[7];
    const float* tp_tab   = (const float*)d_in[8];
    const float* cs_tab   = (const float*)d_in[9];
    const float* Wc       = (const float*)d_in[10];
    const float* asrc_c   = (const float*)d_in[11];
    const float* adst_c   = (const float*)d_in[12];
    const float* wd_c     = (const float*)d_in[13];
    const float* Wco      = (const float*)d_in[14];
    const float* asrc_co  = (const float*)d_in[15];
    const float* adst_co  = (const float*)d_in[16];
    const float* wd_co    = (const float*)d_in[17];
    const float* Wp       = (const float*)d_in[18];
    const float* bp       = (const float*)d_in[19];
    const float* vpd      = (const float*)d_in[20];
    const float* vpf      = (const float*)d_in[21];
    float* out = (float*)d_out;

    float *px, *pcomp, *pcoop, *pxp;
    cudaGetSymbolAddress((void**)&px,    g_x);
    cudaGetSymbolAddress((void**)&pcomp, g_comp);
    cudaGetSymbolAddress((void**)&pcoop, g_coop);
    cudaGetSymbolAddress((void**)&pxp,   g_xp);

    detect_kernel<<<1, 256>>>((const unsigned char*)adjc, 32000);
    distT_kernel<<<dim3(32, 32), dim3(32, 8)>>>(dist);
    buildx_kernel<<<BN / 256 + 1, 256>>>(op_idx, vf, cs_tab, tp_tab);

    adjT_kernel<<<dim3(32, 32, BB), dim3(32, 8)>>>(adjc);
    h_kernel<<<BN / 4, 256>>>(px, 15, (const float*)nullptr, 0, Wc, asrc_c, adst_c);
    gat_kernel<<<dim3((NN + 31) / 32, BB), 256>>>(wd_c, pcomp);

    adjT_kernel<<<dim3(32, 32, BB), dim3(32, 8)>>>(adjo);
    h_kernel<<<BN / 4, 256>>>(px, 15, pcomp, 64, Wco, asrc_co, adst_co);
    gat_kernel<<<dim3((NN + 31) / 32, BB), 256>>>(wd_co, pcoop);

    xp_kernel<<<BN / 8, 256>>>(time_idx, op_idx, vf, time_tab, cs_tab, tp_tab, Wp, bp, pxp);
    scores_kernel<<<BN / 8, 256>>>(pxp, vpd, vpf);
    pool_kernel<<<dim3(BB, 2), 256>>>(pxp, dpcs, out);
}